// round 16
// baseline (speedup 1.0000x reference)
#include <cuda_runtime.h>
#include <cuda_fp16.h>
#include <cstdint>

#define IN_UNITS 256
#define H1 128
#define H2 64
#define MAX_ROWS 16384

#define H1_STRIDE 272
#define W2_STRIDE 144
// ---- edge kernel smem (per CTA: 4 pairs x 32 edges) ----
#define E_H1   0                                    // 4 x 32 x 272 = 34816
#define E_W2   34816                                // 128 x 144 = 18432
#define E_BW   (E_W2 + 18432)                       // 53248: 64 float2
#define E_PB   (E_BW + 512)                         // 53760: 4 pairs x 32 floats
#define E_SMEM (E_PB + 1024)                        // 54784 -> 3 CTAs/SM

// ---- precompute kernel smem (R10, proven) ----
#define PRE_W1    0
#define PRE_FEAT  (256 * 272)                       // 69632
#define PRE_B1    (PRE_FEAT + 128 * 528)            // 137216
#define PRE_SMEM  (PRE_B1 + 128 * 4)                // 137728 -> 1 CTA/SM

__device__ __align__(16) __half g_Ah[MAX_ROWS * H1];
__device__ __align__(16) __half g_Bh[MAX_ROWS * H1];

// ---------------------------------------------------------------------------
__device__ __forceinline__ uint32_t smem_u32(const void* p) {
    uint32_t a;
    asm("{ .reg .u64 t; cvta.to.shared.u64 t, %1; cvt.u32.u64 %0, t; }"
        : "=r"(a) : "l"(p));
    return a;
}
__device__ __forceinline__ void ldsm_x4(uint32_t* r, uint32_t a) {
    asm volatile("ldmatrix.sync.aligned.m8n8.x4.shared.b16 {%0,%1,%2,%3}, [%4];"
                 : "=r"(r[0]), "=r"(r[1]), "=r"(r[2]), "=r"(r[3]) : "r"(a));
}
__device__ __forceinline__ void ldsm_x4_t(uint32_t* r, uint32_t a) {
    asm volatile("ldmatrix.sync.aligned.m8n8.x4.trans.shared.b16 {%0,%1,%2,%3}, [%4];"
                 : "=r"(r[0]), "=r"(r[1]), "=r"(r[2]), "=r"(r[3]) : "r"(a));
}
__device__ __forceinline__ void mma_f16(float* c, const uint32_t* a,
                                        uint32_t b0, uint32_t b1) {
    asm volatile(
        "mma.sync.aligned.m16n8k16.row.col.f32.f16.f16.f32 "
        "{%0,%1,%2,%3}, {%4,%5,%6,%7}, {%8,%9}, {%0,%1,%2,%3};"
        : "+f"(c[0]), "+f"(c[1]), "+f"(c[2]), "+f"(c[3])
        : "r"(a[0]), "r"(a[1]), "r"(a[2]), "r"(a[3]), "r"(b0), "r"(b1));
}
__device__ __forceinline__ uint32_t hadd2relu(uint32_t a, uint32_t b) {
    __half2 s = __hadd2(*(__half2*)&a, *(__half2*)&b);
    __half2 z = __float2half2_rn(0.f);
    __half2 r = __hmax2(s, z);
    return *(uint32_t*)&r;
}
__device__ __forceinline__ void pair_bar(int pid) {
    asm volatile("bar.sync %0, 64;" :: "r"(pid + 1) : "memory");
}

// ---------------------------------------------------------------------------
// Kernel 1: layer-1 partials as fp16 mma GEMM (R10 body, proven).
// ---------------------------------------------------------------------------
__global__ void __launch_bounds__(256, 1) precompute_mma(
    const float* __restrict__ drug, const float* __restrict__ dis,
    const float* __restrict__ W1, const float* __restrict__ b1,
    __half* __restrict__ gA, __half* __restrict__ gB,
    int n_drug, int n_dis, int nblkA)
{
    extern __shared__ char smem[];
    const int tid = threadIdx.x, wid = tid >> 5, lid = tid & 31;

    const int isB = (blockIdx.x >= nblkA);
    const float* feat   = isB ? dis : drug;
    const float* W1part = isB ? (W1 + IN_UNITS * H1) : W1;
    __half* outPre      = isB ? gB : gA;
    const int nrows     = isB ? n_dis : n_drug;
    const int blk       = isB ? (blockIdx.x - nblkA) : blockIdx.x;
    const int row0      = blk * 128;

    for (int l = tid; l < 8192; l += 256) {
        const int k = l >> 5, o4 = l & 31;
        float4 v = *(const float4*)(W1part + k * H1 + o4 * 4);
        __half2 h0 = __floats2half2_rn(v.x, v.y);
        __half2 h1 = __floats2half2_rn(v.z, v.w);
        *(uint2*)(smem + PRE_W1 + k * 272 + o4 * 8) =
            make_uint2(*(uint32_t*)&h0, *(uint32_t*)&h1);
    }
    for (int l = tid; l < 8192; l += 256) {
        const int r = l >> 6, c4 = l & 63;
        float4 v = make_float4(0.f, 0.f, 0.f, 0.f);
        if (row0 + r < nrows)
            v = *(const float4*)(feat + (size_t)(row0 + r) * IN_UNITS + c4 * 4);
        __half2 h0 = __floats2half2_rn(v.x, v.y);
        __half2 h1 = __floats2half2_rn(v.z, v.w);
        *(uint2*)(smem + PRE_FEAT + r * 528 + c4 * 8) =
            make_uint2(*(uint32_t*)&h0, *(uint32_t*)&h1);
    }
    if (tid < 128) ((float*)(smem + PRE_B1))[tid] = isB ? 0.f : b1[tid];
    __syncthreads();

    const uint32_t sb = smem_u32(smem);
    const uint32_t fw = sb + PRE_FEAT + wid * 16 * 528;
    const uint32_t a_off = (lid & 15) * 528 + (lid >> 4) * 16;
    const uint32_t b_row = ((lid >> 3) & 1) * 8 + (lid & 7);
    const uint32_t b_nt  = (lid >> 4);

    float acc[16][4];
#pragma unroll
    for (int nt = 0; nt < 16; nt++)
#pragma unroll
        for (int c = 0; c < 4; c++) acc[nt][c] = 0.f;

#pragma unroll 4
    for (int ks = 0; ks < 16; ks++) {
        uint32_t am[4];
        ldsm_x4(am, fw + a_off + ks * 32);
#pragma unroll
        for (int np = 0; np < 8; np++) {
            const uint32_t brow = (ks * 16 + b_row) * 272 + (np * 2 + b_nt) * 16;
            uint32_t bm[4];
            ldsm_x4_t(bm, sb + PRE_W1 + brow);
            mma_f16(acc[np * 2],     am, bm[0], bm[1]);
            mma_f16(acc[np * 2 + 1], am, bm[2], bm[3]);
        }
    }

    const float* b1s = (const float*)(smem + PRE_B1);
    const int r  = lid >> 2;
    const int c2 = (lid & 3) * 2;
#pragma unroll
    for (int nt = 0; nt < 16; nt++) {
        const int col = nt * 8 + c2;
        const float bx = b1s[col], by = b1s[col + 1];
        const int ra = row0 + wid * 16 + r;
        if (ra < nrows) {
            __half2 v = __floats2half2_rn(acc[nt][0] + bx, acc[nt][1] + by);
            *(__half2*)(outPre + (size_t)ra * H1 + col) = v;
        }
        const int rb = ra + 8;
        if (rb < nrows) {
            __half2 v = __floats2half2_rn(acc[nt][2] + bx, acc[nt][3] + by);
            *(__half2*)(outPre + (size_t)rb * H1 + col) = v;
        }
    }
}

// ---------------------------------------------------------------------------
// Kernel 2: per-edge MLP. Warp-pair n-split (acc 32 regs), B from smem,
// __launch_bounds__(256,3) -> <=85 regs -> 3 CTAs/SM -> 24 warps/SM.
// Spends idle L1 bandwidth (60% in R14) to buy +50% latency hiding.
// ---------------------------------------------------------------------------
__global__ void __launch_bounds__(256, 3) edge_kernel(
    const int* __restrict__ src, const int* __restrict__ dst,
    const float* __restrict__ W2, const float* __restrict__ b2,
    const float* __restrict__ W3, const float* __restrict__ b3,
    float* __restrict__ out, int E, int nwt)
{
    extern __shared__ char smem[];
    const int tid = threadIdx.x, wid = tid >> 5, lid = tid & 31;
    const uint32_t sb = smem_u32(smem);

    for (int l = tid; l < H1 * H2; l += 256) {
        const int k = l >> 6, o = l & 63;
        *(__half*)(smem + E_W2 + k * W2_STRIDE + o * 2) = __float2half(W2[l]);
    }
    for (int l = tid; l < H2; l += 256)
        ((float2*)(smem + E_BW))[l] = make_float2(b2[l], W3[l]);
    __syncthreads();

    const int pid  = wid >> 1;        // pair 0..3
    const int wsub = wid & 1;         // n-half: outputs wsub*32 .. +32

    const float b3s = __ldg(b3);
    const uint32_t h1s = sb + E_H1 + pid * 32 * H1_STRIDE;
    char* h1p = smem + E_H1 + pid * 32 * H1_STRIDE;
    float* pb = (float*)(smem + E_PB) + pid * 32;

    const int half = lid >> 4;
    const int s    = lid & 15;
    const uint32_t a_off = (lid & 15) * H1_STRIDE + (lid >> 4) * 16;
    const uint32_t b_row = ((lid >> 3) & 1) * 8 + (lid & 7);
    const uint32_t b_nt  = (lid >> 4);

    const int gw = blockIdx.x * 4 + pid;
    const int gstride = gridDim.x * 4;

    for (int wt = gw; wt < nwt; wt += gstride) {
        const int e0 = wt * 32;

        // ---- gather: this warp fills rows wsub*16..+16 of the pair tile ----
#pragma unroll 4
        for (int i2 = 0; i2 < 8; i2++) {
            const int ei0 = e0 + wsub * 16 + i2 * 2;
            int s0, s1, d0, d1;
            if (ei0 + 1 < E) {
                int2 sp = *(const int2*)(src + ei0);
                int2 dp = *(const int2*)(dst + ei0);
                s0 = sp.x; s1 = sp.y; d0 = dp.x; d1 = dp.y;
            } else {
                int a0 = min(ei0, E - 1), a1 = min(ei0 + 1, E - 1);
                s0 = src[a0]; s1 = src[a1]; d0 = dst[a0]; d1 = dst[a1];
            }
            const int sI = half ? s1 : s0;
            const int dI = half ? d1 : d0;
            const uint4 av = *(const uint4*)(g_Ah + (size_t)sI * H1 + s * 8);
            const uint4 bv = *(const uint4*)(g_Bh + (size_t)dI * H1 + s * 8);
            uint4 hv;
            hv.x = hadd2relu(av.x, bv.x);
            hv.y = hadd2relu(av.y, bv.y);
            hv.z = hadd2relu(av.z, bv.z);
            hv.w = hadd2relu(av.w, bv.w);
            *(uint4*)(h1p + (wsub * 16 + i2 * 2 + half) * H1_STRIDE + s * 16) = hv;
        }
        pair_bar(pid);

        // ---- mma: 8 ks x 2 m-tiles x 2 np; B from smem (this warp's half) ----
        float acc[2][4][4];
#pragma unroll
        for (int mt = 0; mt < 2; mt++)
#pragma unroll
            for (int nt = 0; nt < 4; nt++)
#pragma unroll
                for (int c = 0; c < 4; c++) acc[mt][nt][c] = 0.f;

#pragma unroll
        for (int ks = 0; ks < 8; ks++) {
            uint32_t a0[4], a1[4];
            ldsm_x4(a0, h1s + a_off + ks * 32);
            ldsm_x4(a1, h1s + 16 * H1_STRIDE + a_off + ks * 32);
#pragma unroll
            for (int np = 0; np < 2; np++) {
                uint32_t bm[4];
                ldsm_x4_t(bm, sb + E_W2 + (ks * 16 + b_row) * W2_STRIDE
                              + wsub * 64 + (np * 2 + b_nt) * 16);
                mma_f16(acc[0][np * 2],     a0, bm[0], bm[1]);
                mma_f16(acc[0][np * 2 + 1], a0, bm[2], bm[3]);
                mma_f16(acc[1][np * 2],     a1, bm[0], bm[1]);
                mma_f16(acc[1][np * 2 + 1], a1, bm[2], bm[3]);
            }
        }

        // ---- epilogue: partial relu(h2+b2).W3, pair-combine, store ----
        const float2* bwt = (const float2*)(smem + E_BW);
        float p[4];
#pragma unroll
        for (int mt = 0; mt < 2; mt++) {
            float pr = 0.f, pr8 = 0.f;
#pragma unroll
            for (int nt = 0; nt < 4; nt++) {
                const int col = wsub * 32 + nt * 8 + (lid & 3) * 2;
                float2 c0 = bwt[col], c1 = bwt[col + 1];
                pr  += fmaxf(acc[mt][nt][0] + c0.x, 0.f) * c0.y
                     + fmaxf(acc[mt][nt][1] + c1.x, 0.f) * c1.y;
                pr8 += fmaxf(acc[mt][nt][2] + c0.x, 0.f) * c0.y
                     + fmaxf(acc[mt][nt][3] + c1.x, 0.f) * c1.y;
            }
            p[mt * 2]     = pr;
            p[mt * 2 + 1] = pr8;
        }
#pragma unroll
        for (int q = 0; q < 4; q++) {
            p[q] += __shfl_xor_sync(0xffffffffu, p[q], 1);
            p[q] += __shfl_xor_sync(0xffffffffu, p[q], 2);
        }
        if (wsub == 0 && (lid & 3) == 0) {
            const int li = lid >> 2;
            pb[li]      = p[0];
            pb[li + 8]  = p[1];
            pb[li + 16] = p[2];
            pb[li + 24] = p[3];
        }
        pair_bar(pid);
        if (wsub == 1 && (lid & 3) == 0) {
            const int li = lid >> 2;
#pragma unroll
            for (int q = 0; q < 4; q++) {
                const int r = e0 + (q >> 1) * 16 + (q & 1) * 8 + li;
                if (r < E) out[r] = pb[li + q * 8] + p[q] + b3s;
            }
        }
    }
}

// ---------------------------------------------------------------------------
extern "C" void kernel_launch(void* const* d_in, const int* in_sizes, int n_in,
                              void* d_out, int out_size)
{
    const float* drug = (const float*)d_in[0];
    const float* dis  = (const float*)d_in[1];
    const int*   src  = (const int*)d_in[2];   // int32 (JAX x64 disabled)
    const int*   dst  = (const int*)d_in[3];
    const float* W1   = (const float*)d_in[4];
    const float* b1   = (const float*)d_in[5];
    const float* W2   = (const float*)d_in[6];
    const float* b2   = (const float*)d_in[7];
    const float* W3   = (const float*)d_in[8];
    const float* b3   = (const float*)d_in[9];

    const int n_drug = in_sizes[0] / IN_UNITS;
    const int n_dis  = in_sizes[1] / IN_UNITS;
    const int E      = in_sizes[2];

    __half *gA = nullptr, *gB = nullptr;
    cudaGetSymbolAddress((void**)&gA, g_Ah);
    cudaGetSymbolAddress((void**)&gB, g_Bh);

    cudaFuncSetAttribute(precompute_mma,
                         cudaFuncAttributeMaxDynamicSharedMemorySize, PRE_SMEM);
    cudaFuncSetAttribute(edge_kernel,
                         cudaFuncAttributeMaxDynamicSharedMemorySize, E_SMEM);

    const int nblkA = (n_drug + 127) / 128;
    const int nblkB = (n_dis + 127) / 128;
    precompute_mma<<<nblkA + nblkB, 256, PRE_SMEM>>>(drug, dis, W1, b1, gA, gB,
                                                     n_drug, n_dis, nblkA);

    const int nwt = (E + 31) / 32;           // 32-edge pair tiles
    int grid = 444;                          // 3 CTAs/SM
    if (grid > (nwt + 3) / 4) grid = (nwt + 3) / 4;
    edge_kernel<<<grid, 256, E_SMEM>>>(src, dst, W2, b2, W3, b3,
                                       (float*)d_out, E, nwt);
}

// round 17
// speedup vs baseline: 1.1904x; 1.1904x over previous
#include <cuda_runtime.h>
#include <cuda_fp16.h>
#include <cstdint>

#define IN_UNITS 256
#define H1 128
#define H2 64
#define MAX_ROWS 16384

#define H1_STRIDE 272
#define W2_STRIDE 144
// ---- edge-phase smem layout (R12, proven best) ----
#define OFF_H1   0
#define OFF_W2   (256 * H1_STRIDE)                  // 69632
#define OFF_BW   (OFF_W2 + 128 * W2_STRIDE)         // 88064
// ---- pre-phase smem layout (overlaps edge area; barrier-separated) ----
#define PW1      0
#define PFEAT    (256 * 272)                        // 69632
#define PB1      (PFEAT + 8 * 16 * 272)             // 104448
#define SMEM_BYTES (PB1 + 512)                      // 104960 -> 2 CTAs/SM

__device__ __align__(16) __half g_Ah[MAX_ROWS * H1];
__device__ __align__(16) __half g_Bh[MAX_ROWS * H1];
__device__ int g_bar_ctr = 0;
__device__ int g_bar_gen = 0;

// ---------------------------------------------------------------------------
__device__ __forceinline__ uint32_t smem_u32(const void* p) {
    uint32_t a;
    asm("{ .reg .u64 t; cvta.to.shared.u64 t, %1; cvt.u32.u64 %0, t; }"
        : "=r"(a) : "l"(p));
    return a;
}
__device__ __forceinline__ void ldsm_x4(uint32_t* r, uint32_t a) {
    asm volatile("ldmatrix.sync.aligned.m8n8.x4.shared.b16 {%0,%1,%2,%3}, [%4];"
                 : "=r"(r[0]), "=r"(r[1]), "=r"(r[2]), "=r"(r[3]) : "r"(a));
}
__device__ __forceinline__ void ldsm_x4_t(uint32_t* r, uint32_t a) {
    asm volatile("ldmatrix.sync.aligned.m8n8.x4.trans.shared.b16 {%0,%1,%2,%3}, [%4];"
                 : "=r"(r[0]), "=r"(r[1]), "=r"(r[2]), "=r"(r[3]) : "r"(a));
}
__device__ __forceinline__ void mma_f16(float* c, const uint32_t* a,
                                        uint32_t b0, uint32_t b1) {
    asm volatile(
        "mma.sync.aligned.m16n8k16.row.col.f32.f16.f16.f32 "
        "{%0,%1,%2,%3}, {%4,%5,%6,%7}, {%8,%9}, {%0,%1,%2,%3};"
        : "+f"(c[0]), "+f"(c[1]), "+f"(c[2]), "+f"(c[3])
        : "r"(a[0]), "r"(a[1]), "r"(a[2]), "r"(a[3]), "r"(b0), "r"(b1));
}
__device__ __forceinline__ uint32_t hadd2relu(uint32_t a, uint32_t b) {
    __half2 s = __hadd2(*(__half2*)&a, *(__half2*)&b);
    __half2 z = __float2half2_rn(0.f);
    __half2 r = __hmax2(s, z);
    return *(uint32_t*)&r;
}
__device__ __forceinline__ void grid_barrier(int tid) {
    __threadfence();
    __syncthreads();
    if (tid == 0) {
        int g0 = *((volatile int*)&g_bar_gen);
        int old = atomicAdd(&g_bar_ctr, 1);
        if (old == (int)gridDim.x - 1) {
            g_bar_ctr = 0;
            __threadfence();
            *((volatile int*)&g_bar_gen) = g0 + 1;
        } else {
            while (*((volatile int*)&g_bar_gen) == g0) { }
        }
        __threadfence();
    }
    __syncthreads();
}

// ---------------------------------------------------------------------------
// Fused (R12 base): phase 1 = layer-1 partials, grid barrier, phase 2 = edge
// MLP. This round: depth-2 software-pipelined loads in both gather loops +
// index hoisting. Numerics identical to R12.
// ---------------------------------------------------------------------------
__global__ void __launch_bounds__(256, 2) fused_kernel(
    const float* __restrict__ drug, const float* __restrict__ dis,
    const int* __restrict__ src, const int* __restrict__ dst,
    const float* __restrict__ W1, const float* __restrict__ b1,
    const float* __restrict__ W2, const float* __restrict__ b2,
    const float* __restrict__ W3, const float* __restrict__ b3,
    float* __restrict__ out, int n_drug, int n_dis, int E, int nwt)
{
    extern __shared__ char smem[];
    const int tid = threadIdx.x, wid = tid >> 5, lid = tid & 31;
    const uint32_t sb = smem_u32(smem);

    const uint32_t b_row = ((lid >> 3) & 1) * 8 + (lid & 7);
    const uint32_t b_nt  = (lid >> 4);

    // ================= Phase 1: precompute =================
    {
        const int halfCTAs = gridDim.x >> 1;
        const int isB = (blockIdx.x >= halfCTAs);
        const float* feat   = isB ? dis : drug;
        const float* W1p    = isB ? (W1 + IN_UNITS * H1) : W1;
        __half* outPre      = isB ? g_Bh : g_Ah;
        const int nrows     = isB ? n_dis : n_drug;

        for (int l = tid; l < 8192; l += 256) {
            const int k = l >> 5, o4 = l & 31;
            float4 v = *(const float4*)(W1p + k * H1 + o4 * 4);
            __half2 h0 = __floats2half2_rn(v.x, v.y);
            __half2 h1 = __floats2half2_rn(v.z, v.w);
            *(uint2*)(smem + PW1 + k * 272 + o4 * 8) =
                make_uint2(*(uint32_t*)&h0, *(uint32_t*)&h1);
        }
        if (tid < 128) ((float*)(smem + PB1))[tid] = isB ? 0.f : b1[tid];
        __syncthreads();

        const int units = (nrows + 15) >> 4;
        const int slotstride = halfCTAs * 8;
        char* fs = smem + PFEAT + wid * 16 * 272;
        const uint32_t fsu = sb + PFEAT + wid * 16 * 272;
        const uint32_t pa_off = (lid & 15) * 272 + (lid >> 4) * 16;
        const float* b1s = (const float*)(smem + PB1);

        for (int u = (blockIdx.x - isB * halfCTAs) * 8 + wid; u < units;
             u += slotstride) {
            const int row0 = u * 16;
            float acc[16][4];
#pragma unroll
            for (int nt = 0; nt < 16; nt++)
#pragma unroll
                for (int c = 0; c < 4; c++) acc[nt][c] = 0.f;

            const bool full = (row0 + 16 <= nrows);
#pragma unroll
            for (int kc = 0; kc < 2; kc++) {
                if (full) {
                    // depth-2 pipelined staging: load r+1 while converting r
                    float4 v = *(const float4*)(feat + (size_t)row0 * IN_UNITS
                                                + kc * 128 + lid * 4);
#pragma unroll
                    for (int r = 0; r < 16; r++) {
                        float4 vn;
                        if (r < 15)
                            vn = *(const float4*)(feat
                                  + (size_t)(row0 + r + 1) * IN_UNITS
                                  + kc * 128 + lid * 4);
                        __half2 h0 = __floats2half2_rn(v.x, v.y);
                        __half2 h1 = __floats2half2_rn(v.z, v.w);
                        *(uint2*)(fs + r * 272 + lid * 8) =
                            make_uint2(*(uint32_t*)&h0, *(uint32_t*)&h1);
                        v = vn;
                    }
                } else {
#pragma unroll
                    for (int r = 0; r < 16; r++) {
                        const int row = row0 + r;
                        float4 v = make_float4(0.f, 0.f, 0.f, 0.f);
                        if (row < nrows)
                            v = *(const float4*)(feat + (size_t)row * IN_UNITS
                                                 + kc * 128 + lid * 4);
                        __half2 h0 = __floats2half2_rn(v.x, v.y);
                        __half2 h1 = __floats2half2_rn(v.z, v.w);
                        *(uint2*)(fs + r * 272 + lid * 8) =
                            make_uint2(*(uint32_t*)&h0, *(uint32_t*)&h1);
                    }
                }
                __syncwarp();
#pragma unroll
                for (int ks = 0; ks < 8; ks++) {
                    uint32_t am[4];
                    ldsm_x4(am, fsu + pa_off + ks * 32);
#pragma unroll
                    for (int np = 0; np < 8; np++) {
                        const uint32_t brow =
                            (kc * 128 + ks * 16 + b_row) * 272
                            + (np * 2 + b_nt) * 16;
                        uint32_t bm[4];
                        ldsm_x4_t(bm, sb + PW1 + brow);
                        mma_f16(acc[np * 2],     am, bm[0], bm[1]);
                        mma_f16(acc[np * 2 + 1], am, bm[2], bm[3]);
                    }
                }
                __syncwarp();
            }

            const int r  = lid >> 2;
            const int c2 = (lid & 3) * 2;
#pragma unroll
            for (int nt = 0; nt < 16; nt++) {
                const int col = nt * 8 + c2;
                const float bx = b1s[col], by = b1s[col + 1];
                const int ra = row0 + r;
                if (ra < nrows) {
                    __half2 v = __floats2half2_rn(acc[nt][0] + bx,
                                                  acc[nt][1] + by);
                    *(__half2*)(outPre + (size_t)ra * H1 + col) = v;
                }
                const int rb = ra + 8;
                if (rb < nrows) {
                    __half2 v = __floats2half2_rn(acc[nt][2] + bx,
                                                  acc[nt][3] + by);
                    *(__half2*)(outPre + (size_t)rb * H1 + col) = v;
                }
            }
        }
    }

    grid_barrier(tid);

    // ================= Phase 2: edge MLP (R12 body, pipelined gather) =====
    for (int l = tid; l < H1 * H2; l += 256) {
        const int k = l >> 6, o = l & 63;
        *(__half*)(smem + OFF_W2 + k * W2_STRIDE + o * 2) = __float2half(W2[l]);
    }
    for (int l = tid; l < H2; l += 256)
        ((float2*)(smem + OFF_BW))[l] = make_float2(b2[l], W3[l]);
    __syncthreads();

    const float b3s = __ldg(b3);
    const uint32_t h1s = sb + OFF_H1 + wid * 32 * H1_STRIDE;
    char* h1p = smem + OFF_H1 + wid * 32 * H1_STRIDE;

    const int half = lid >> 4;
    const int s    = lid & 15;
    const uint32_t a_off = (lid & 15) * H1_STRIDE + (lid >> 4) * 16;

    const int gw = blockIdx.x * 8 + wid;
    const int gstride = gridDim.x * 8;

    for (int wt = gw; wt < nwt; wt += gstride) {
        const int e0 = wt * 32;

        if (e0 + 32 <= E) {
            // ---- interior tile: index hoist + depth-2 pipelined gather ----
            int4 sp4[8], dp4[8];
#pragma unroll
            for (int q = 0; q < 8; q++) {
                sp4[q] = *(const int4*)(src + e0 + q * 4);
                dp4[q] = *(const int4*)(dst + e0 + q * 4);
            }
            uint4 av, bv;
            {
                const int sI = half ? sp4[0].y : sp4[0].x;
                const int dI = half ? dp4[0].y : dp4[0].x;
                av = *(const uint4*)(g_Ah + (size_t)sI * H1 + s * 8);
                bv = *(const uint4*)(g_Bh + (size_t)dI * H1 + s * 8);
            }
#pragma unroll
            for (int i2 = 0; i2 < 16; i2++) {
                uint4 avn, bvn;
                if (i2 < 15) {
                    const int4 sq = sp4[(i2 + 1) >> 1];
                    const int4 dq = dp4[(i2 + 1) >> 1];
                    int sI, dI;
                    if ((i2 + 1) & 1) {           // compile-time per iteration
                        sI = half ? sq.w : sq.z;
                        dI = half ? dq.w : dq.z;
                    } else {
                        sI = half ? sq.y : sq.x;
                        dI = half ? dq.y : dq.x;
                    }
                    avn = *(const uint4*)(g_Ah + (size_t)sI * H1 + s * 8);
                    bvn = *(const uint4*)(g_Bh + (size_t)dI * H1 + s * 8);
                }
                uint4 hv;
                hv.x = hadd2relu(av.x, bv.x);
                hv.y = hadd2relu(av.y, bv.y);
                hv.z = hadd2relu(av.z, bv.z);
                hv.w = hadd2relu(av.w, bv.w);
                *(uint4*)(h1p + (i2 * 2 + half) * H1_STRIDE + s * 16) = hv;
                av = avn; bv = bvn;
            }
        } else {
            // ---- tail tile (<=1 per warp-slot): original guarded path ----
            for (int i2 = 0; i2 < 16; i2++) {
                const int ei0 = e0 + i2 * 2;
                int a0 = min(ei0, E - 1), a1 = min(ei0 + 1, E - 1);
                int s0 = src[a0], s1 = src[a1], d0 = dst[a0], d1 = dst[a1];
                const int sI = half ? s1 : s0;
                const int dI = half ? d1 : d0;
                const uint4 avv = *(const uint4*)(g_Ah + (size_t)sI * H1 + s * 8);
                const uint4 bvv = *(const uint4*)(g_Bh + (size_t)dI * H1 + s * 8);
                uint4 hv;
                hv.x = hadd2relu(avv.x, bvv.x);
                hv.y = hadd2relu(avv.y, bvv.y);
                hv.z = hadd2relu(avv.z, bvv.z);
                hv.w = hadd2relu(avv.w, bvv.w);
                *(uint4*)(h1p + (i2 * 2 + half) * H1_STRIDE + s * 16) = hv;
            }
        }
        __syncwarp();

        float acc[2][8][4];
#pragma unroll
        for (int mt = 0; mt < 2; mt++)
#pragma unroll
            for (int nt = 0; nt < 8; nt++)
#pragma unroll
                for (int c = 0; c < 4; c++) acc[mt][nt][c] = 0.f;

#pragma unroll
        for (int ks = 0; ks < 8; ks++) {
            uint32_t a0[4], a1[4];
            ldsm_x4(a0, h1s + a_off + ks * 32);
            ldsm_x4(a1, h1s + 16 * H1_STRIDE + a_off + ks * 32);
#pragma unroll
            for (int ntp = 0; ntp < 4; ntp++) {
                const uint32_t brow = (ks * 16 + b_row) * W2_STRIDE
                                    + (ntp * 2 + b_nt) * 16;
                uint32_t bm[4];
                ldsm_x4_t(bm, sb + OFF_W2 + brow);
                mma_f16(acc[0][ntp * 2],     a0, bm[0], bm[1]);
                mma_f16(acc[0][ntp * 2 + 1], a0, bm[2], bm[3]);
                mma_f16(acc[1][ntp * 2],     a1, bm[0], bm[1]);
                mma_f16(acc[1][ntp * 2 + 1], a1, bm[2], bm[3]);
            }
        }

        const float2* bwt = (const float2*)(smem + OFF_BW);
#pragma unroll
        for (int mt = 0; mt < 2; mt++) {
            float pr = 0.f, pr8 = 0.f;
#pragma unroll
            for (int nt = 0; nt < 8; nt++) {
                const int col = nt * 8 + (lid & 3) * 2;
                float2 c0 = bwt[col], c1 = bwt[col + 1];
                pr  += fmaxf(acc[mt][nt][0] + c0.x, 0.f) * c0.y
                     + fmaxf(acc[mt][nt][1] + c1.x, 0.f) * c1.y;
                pr8 += fmaxf(acc[mt][nt][2] + c0.x, 0.f) * c0.y
                     + fmaxf(acc[mt][nt][3] + c1.x, 0.f) * c1.y;
            }
            pr  += __shfl_xor_sync(0xffffffffu, pr, 1);
            pr  += __shfl_xor_sync(0xffffffffu, pr, 2);
            pr8 += __shfl_xor_sync(0xffffffffu, pr8, 1);
            pr8 += __shfl_xor_sync(0xffffffffu, pr8, 2);
            if ((lid & 3) == 0) {
                const int r = e0 + mt * 16 + (lid >> 2);
                if (r < E)     out[r]     = pr + b3s;
                if (r + 8 < E) out[r + 8] = pr8 + b3s;
            }
        }
        __syncwarp();
    }
}

// ---------------------------------------------------------------------------
extern "C" void kernel_launch(void* const* d_in, const int* in_sizes, int n_in,
                              void* d_out, int out_size)
{
    const float* drug = (const float*)d_in[0];
    const float* dis  = (const float*)d_in[1];
    const int*   src  = (const int*)d_in[2];   // int32 (JAX x64 disabled)
    const int*   dst  = (const int*)d_in[3];
    const float* W1   = (const float*)d_in[4];
    const float* b1   = (const float*)d_in[5];
    const float* W2   = (const float*)d_in[6];
    const float* b2   = (const float*)d_in[7];
    const float* W3   = (const float*)d_in[8];
    const float* b3   = (const float*)d_in[9];

    const int n_drug = in_sizes[0] / IN_UNITS;
    const int n_dis  = in_sizes[1] / IN_UNITS;
    const int E      = in_sizes[2];
    const int nwt    = (E + 31) / 32;

    cudaFuncSetAttribute(fused_kernel,
                         cudaFuncAttributeMaxDynamicSharedMemorySize, SMEM_BYTES);

    // grid = 296: exactly 2 CTAs/SM resident -> grid barrier cannot deadlock.
    fused_kernel<<<296, 256, SMEM_BYTES>>>(drug, dis, src, dst, W1, b1, W2, b2,
                                           W3, b3, (float*)d_out,
                                           n_drug, n_dis, E, nwt);
}